// round 6
// baseline (speedup 1.0000x reference)
#include <cuda_runtime.h>
#include <cuda_bf16.h>
#include <cstdint>

#define T_LEN 2048
#define C_DIM 2048
#define H_NUM 16
#define N_DIM 128
#define KVH_NUM 4
#define HN_DIM 2048
#define KVN_DIM 512

// fused stage-1 output column offsets
#define OFF_XR 0
#define OFF_XK 2048
#define OFF_XV 2560
#define OFF_TW 3072
#define OFF_TA 3232
#define OFF_TV 3328
#define OFF_TK 3392
#define OFF_TG 3456
#define NCAT 3616
#define NMID 544

// stage-2 A' regions inside g_Ap (element offsets)
#define APW_BASE 0
#define APA_BASE 983040
#define APG_BASE 1572864
#define APV_BASE 2555904
#define APK_BASE 2949120

// ---------------- scratch ----------------
__device__ float g_Ccat[(size_t)T_LEN * NCAT];
__device__ float g_wfull[T_LEN * HN_DIM];
__device__ float g_afull[T_LEN * HN_DIM];
__device__ float g_gfull[T_LEN * HN_DIM];
__device__ float g_vmix[T_LEN * KVN_DIM];
__device__ float g_kmix[T_LEN * KVN_DIM];
__device__ float g_rr[T_LEN * HN_DIM];
__device__ float g_kf[T_LEN * KVN_DIM];
__device__ float g_vf[T_LEN * KVN_DIM];
__device__ float g_kk[T_LEN * KVN_DIM];
__device__ float g_wd[T_LEN * HN_DIM];
__device__ float g_bb[T_LEN * HN_DIM];
__device__ float g_coef[T_LEN * H_NUM];
__device__ float g_c1[T_LEN * H_NUM];
__device__ float g_c2[T_LEN * H_NUM];
__device__ float g_y[T_LEN * HN_DIM];

__device__ __nv_bfloat16 g_Ap[(size_t)2048 * 3 * 2048];
__device__ __nv_bfloat16 g_Bp[(size_t)3 * 2048 * NCAT];

// ---------------- helpers ----------------
__device__ __forceinline__ float sigmoidf_(float x) { return 1.0f / (1.0f + expf(-x)); }

__device__ __forceinline__ float blockReduceSum128(float v, float* red) {
#pragma unroll
    for (int m = 16; m > 0; m >>= 1) v += __shfl_xor_sync(0xffffffffu, v, m);
    __syncthreads();
    if ((threadIdx.x & 31) == 0) red[threadIdx.x >> 5] = v;
    __syncthreads();
    return red[0] + red[1] + red[2] + red[3];
}

// packed f32x2 ops (sm_103a)
__device__ __forceinline__ unsigned long long pack2(float x, float y) {
    unsigned long long r;
    asm("mov.b64 %0, {%1, %2};" : "=l"(r) : "f"(x), "f"(y));
    return r;
}
__device__ __forceinline__ float2 unpack2(unsigned long long v) {
    float x, y;
    asm("mov.b64 {%0, %1}, %2;" : "=f"(x), "=f"(y) : "l"(v));
    return make_float2(x, y);
}
__device__ __forceinline__ unsigned long long fma2_(unsigned long long a, unsigned long long b,
                                                    unsigned long long c) {
    unsigned long long d;
    asm("fma.rn.f32x2 %0, %1, %2, %3;" : "=l"(d) : "l"(a), "l"(b), "l"(c));
    return d;
}
__device__ __forceinline__ unsigned long long mul2_(unsigned long long a, unsigned long long b) {
    unsigned long long d;
    asm("mul.rn.f32x2 %0, %1, %2;" : "=l"(d) : "l"(a), "l"(b));
    return d;
}
__device__ __forceinline__ unsigned long long add2_(unsigned long long a, unsigned long long b) {
    unsigned long long d;
    asm("add.rn.f32x2 %0, %1, %2;" : "=l"(d) : "l"(a), "l"(b));
    return d;
}

__device__ __forceinline__ uint32_t packsplit_hi(float a, float b) {
    __nv_bfloat162 h = __floats2bfloat162_rn(a, b);
    return *(uint32_t*)&h;
}
__device__ __forceinline__ uint32_t packsplit_lo(float a, float b, uint32_t hipack) {
    __nv_bfloat162* hp = (__nv_bfloat162*)&hipack;
    float ra = a - __bfloat162float(hp->x);
    float rb = b - __bfloat162float(hp->y);
    __nv_bfloat162 l = __floats2bfloat162_rn(ra, rb);
    return *(uint32_t*)&l;
}

// ---------------- split conversions ----------------
__global__ void splitAmask_kernel(const float* __restrict__ x, const float* __restrict__ mask,
                                  __nv_bfloat16* __restrict__ Ap, int n2) {
    int i = blockIdx.x * blockDim.x + threadIdx.x;
    if (i >= n2) return;
    int i2 = i * 2;
    int r = i2 >> 11, c = i2 & 2047;
    float2 xv = *(const float2*)&x[i2];
    float m = mask[r];
    float v0 = xv.x * m, v1 = xv.y * m;
    uint32_t hi = packsplit_hi(v0, v1);
    uint32_t lo = packsplit_lo(v0, v1, hi);
    size_t base = (size_t)r * 6144 + c;
    *(uint32_t*)&Ap[base] = hi;
    *(uint32_t*)&Ap[base + 2048] = lo;
    *(uint32_t*)&Ap[base + 4096] = hi;
}

// one fused kernel for the whole stage-1 concat B' (all 8 matrices, K=2048)
__global__ void splitBcat_kernel(const float* __restrict__ W_r, const float* __restrict__ W_k,
                                 const float* __restrict__ W_v, const float* __restrict__ w1,
                                 const float* __restrict__ a1, const float* __restrict__ v1,
                                 const float* __restrict__ k1, const float* __restrict__ g1,
                                 __nv_bfloat16* __restrict__ Bp, int n2) {
    int i = blockIdx.x * blockDim.x + threadIdx.x;
    if (i >= n2) return;
    int i2 = i * 2;
    int r = i2 / NCAT, c = i2 - r * NCAT;
    const float* src;
    int off, ncols;
    if (c < 2048) { src = W_r; off = OFF_XR; ncols = 2048; }
    else if (c < 2560) { src = W_k; off = OFF_XK; ncols = 512; }
    else if (c < 3072) { src = W_v; off = OFF_XV; ncols = 512; }
    else if (c < 3232) { src = w1; off = OFF_TW; ncols = 160; }
    else if (c < 3328) { src = a1; off = OFF_TA; ncols = 96; }
    else if (c < 3392) { src = v1; off = OFF_TV; ncols = 64; }
    else if (c < 3456) { src = k1; off = OFF_TK; ncols = 64; }
    else { src = g1; off = OFF_TG; ncols = 160; }
    float2 xv = *(const float2*)&src[(size_t)r * ncols + (c - off)];
    uint32_t hi = packsplit_hi(xv.x, xv.y);
    uint32_t lo = packsplit_lo(xv.x, xv.y, hi);
    size_t base = (size_t)r * NCAT + c;
    *(uint32_t*)&Bp[base] = hi;
    *(uint32_t*)&Bp[base + (size_t)2048 * NCAT] = hi;
    *(uint32_t*)&Bp[base + (size_t)4096 * NCAT] = lo;
}

// generic B split (stage-2/final)
__global__ void splitB_kernel(const float* __restrict__ B, __nv_bfloat16* __restrict__ Bp,
                              int K, int Ncols, int ldB, int colOff, int n2) {
    int i = blockIdx.x * blockDim.x + threadIdx.x;
    if (i >= n2) return;
    int i2 = i * 2;
    int r = i2 / Ncols, c = i2 - r * Ncols;
    float2 xv = *(const float2*)&B[i2];
    uint32_t hi = packsplit_hi(xv.x, xv.y);
    uint32_t lo = packsplit_lo(xv.x, xv.y, hi);
    size_t base = (size_t)r * ldB + colOff + c;
    *(uint32_t*)&Bp[base] = hi;
    *(uint32_t*)&Bp[base + (size_t)K * ldB] = hi;
    *(uint32_t*)&Bp[base + (size_t)2 * K * ldB] = lo;
}

// ---------------- fused act + stage-2 A-split from Ccat ----------------
__global__ void splitMids_kernel(const float* __restrict__ Ccat, __nv_bfloat16* __restrict__ Ap,
                                 int n2) {
    int i = blockIdx.x * blockDim.x + threadIdx.x;
    if (i >= n2) return;
    int i2 = i * 2;
    int t = i2 / NMID, c = i2 - t * NMID;
    const float* src = &Ccat[(size_t)t * NCAT + OFF_TW];
    float v0 = src[c], v1 = src[c + 1];
    int K, lc;
    size_t base;
    if (c < 160) {
        v0 = tanhf(v0); v1 = tanhf(v1);
        K = 160; base = APW_BASE; lc = c;
    } else if (c < 256) {
        K = 96; base = APA_BASE; lc = c - 160;
    } else if (c < 320) {
        K = 64; base = APV_BASE; lc = c - 256;
    } else if (c < 384) {
        K = 64; base = APK_BASE; lc = c - 320;
    } else {
        v0 = sigmoidf_(v0); v1 = sigmoidf_(v1);
        K = 160; base = APG_BASE; lc = c - 384;
    }
    uint32_t hi = packsplit_hi(v0, v1);
    uint32_t lo = packsplit_lo(v0, v1, hi);
    size_t off = base + (size_t)t * (3 * K) + lc;
    *(uint32_t*)&Ap[off] = hi;
    *(uint32_t*)&Ap[off + K] = lo;
    *(uint32_t*)&Ap[off + 2 * K] = hi;
}

// ---------------- fused merge + final A-split ----------------
__global__ void mergeSplitA_kernel(const float* __restrict__ y, const float* __restrict__ coef,
                                   const float* __restrict__ vf, const float* __restrict__ gbuf,
                                   __nv_bfloat16* __restrict__ Ap, int n2) {
    int i = blockIdx.x * blockDim.x + threadIdx.x;
    if (i >= n2) return;
    int i2 = i * 2;
    int t = i2 >> 11, hn = i2 & 2047;
    int h = hn >> 7, nn = hn & 127;
    float cf = coef[t * H_NUM + h];
    const float* vp = &vf[t * KVN_DIM + (h >> 2) * 128 + nn];
    float2 yv = *(const float2*)&y[i2];
    float2 gv = *(const float2*)&gbuf[i2];
    float v0 = (yv.x + cf * vp[0]) * gv.x;
    float v1 = (yv.y + cf * vp[1]) * gv.y;
    uint32_t hi = packsplit_hi(v0, v1);
    uint32_t lo = packsplit_lo(v0, v1, hi);
    size_t base = (size_t)t * 6144 + hn;
    *(uint32_t*)&Ap[base] = hi;
    *(uint32_t*)&Ap[base + 2048] = lo;
    *(uint32_t*)&Ap[base + 4096] = hi;
}

// ---------------- bf16 tensor-core GEMM, 3-stage cp.async pipeline ----------------
#define LDA_S 40
#define LDB_S 136
#define NSTAGE 3

__global__ __launch_bounds__(256) void bf16_gemm_kernel(
    const __nv_bfloat16* __restrict__ A, const __nv_bfloat16* __restrict__ B,
    float* __restrict__ C, int M, int N, int K3, int ldB, int ldC) {
    __shared__ __align__(16) __nv_bfloat16 As[NSTAGE][128 * LDA_S];
    __shared__ __align__(16) __nv_bfloat16 Bs[NSTAGE][32 * LDB_S];

    const int tid = threadIdx.x;
    const int bm = blockIdx.y * 128;
    const int bn = blockIdx.x * 128;
    const int warp = tid >> 5;
    const int lane = tid & 31;
    const int wm = warp & 3;
    const int wn = warp >> 2;

    const int ar = tid >> 2;
    const int ac = (tid & 3) * 8;
    const int br = tid >> 4;
    const int bc = (tid & 15) * 8;
    const int bsz = ((bn + bc) < N) ? 16 : 0;

    float c[2][8][4];
#pragma unroll
    for (int mi = 0; mi < 2; mi++)
#pragma unroll
        for (int ni = 0; ni < 8; ni++)
#pragma unroll
            for (int q = 0; q < 4; q++) c[mi][ni][q] = 0.0f;

    const int KT = K3 >> 5;

    auto load_stage = [&](int st, int kt) {
        int k0 = kt * 32;
#pragma unroll
        for (int it = 0; it < 2; it++) {
            const __nv_bfloat16* src = A + (size_t)(bm + ar + it * 64) * K3 + k0 + ac;
            uint32_t dst = (uint32_t)__cvta_generic_to_shared(&As[st][(ar + it * 64) * LDA_S + ac]);
            asm volatile("cp.async.ca.shared.global [%0], [%1], 16;\n" ::"r"(dst), "l"(src));
        }
#pragma unroll
        for (int it = 0; it < 2; it++) {
            const __nv_bfloat16* src = B + (size_t)(k0 + br + it * 16) * ldB + bn + bc;
            uint32_t dst = (uint32_t)__cvta_generic_to_shared(&Bs[st][(br + it * 16) * LDB_S + bc]);
            asm volatile("cp.async.ca.shared.global [%0], [%1], 16, %2;\n" ::"r"(dst), "l"(src),
                         "r"(bsz));
        }
        asm volatile("cp.async.commit_group;\n");
    };

    auto compute_stage = [&](int st) {
#pragma unroll
        for (int kk = 0; kk < 32; kk += 16) {
            uint32_t af[2][4];
#pragma unroll
            for (int mi = 0; mi < 2; mi++) {
                uint32_t addr = (uint32_t)__cvta_generic_to_shared(
                    &As[st][(wm * 32 + mi * 16 + (lane & 15)) * LDA_S + kk + (lane >> 4) * 8]);
                asm volatile("ldmatrix.sync.aligned.m8n8.x4.shared.b16 {%0,%1,%2,%3}, [%4];\n"
                             : "=r"(af[mi][0]), "=r"(af[mi][1]), "=r"(af[mi][2]), "=r"(af[mi][3])
                             : "r"(addr));
            }
            uint32_t bfr[8][2];
#pragma unroll
            for (int p = 0; p < 4; p++) {
                uint32_t addr = (uint32_t)__cvta_generic_to_shared(
                    &Bs[st][(kk + (lane & 15)) * LDB_S + wn * 64 + p * 16 + (lane >> 4) * 8]);
                uint32_t b0, b1, b2, b3;
                asm volatile("ldmatrix.sync.aligned.m8n8.x4.trans.shared.b16 {%0,%1,%2,%3}, [%4];\n"
                             : "=r"(b0), "=r"(b1), "=r"(b2), "=r"(b3)
                             : "r"(addr));
                bfr[p * 2][0] = b0;
                bfr[p * 2][1] = b1;
                bfr[p * 2 + 1][0] = b2;
                bfr[p * 2 + 1][1] = b3;
            }
#pragma unroll
            for (int mi = 0; mi < 2; mi++)
#pragma unroll
                for (int ni = 0; ni < 8; ni++) {
                    asm volatile(
                        "mma.sync.aligned.m16n8k16.row.col.f32.bf16.bf16.f32 "
                        "{%0,%1,%2,%3}, {%4,%5,%6,%7}, {%8,%9}, {%0,%1,%2,%3};\n"
                        : "+f"(c[mi][ni][0]), "+f"(c[mi][ni][1]), "+f"(c[mi][ni][2]),
                          "+f"(c[mi][ni][3])
                        : "r"(af[mi][0]), "r"(af[mi][1]), "r"(af[mi][2]), "r"(af[mi][3]),
                          "r"(bfr[ni][0]), "r"(bfr[ni][1]));
                }
        }
    };

    load_stage(0, 0);
    if (KT > 1) load_stage(1, 1);
    for (int kt = 0; kt < KT; kt++) {
        if (kt + 2 < KT) {
            load_stage((kt + 2) % NSTAGE, kt + 2);
            asm volatile("cp.async.wait_group 2;\n");
        } else if (kt + 1 < KT) {
            asm volatile("cp.async.wait_group 1;\n");
        } else {
            asm volatile("cp.async.wait_group 0;\n");
        }
        __syncthreads();
        compute_stage(kt % NSTAGE);
        __syncthreads();
    }

#pragma unroll
    for (int mi = 0; mi < 2; mi++) {
        int row = bm + wm * 32 + mi * 16 + (lane >> 2);
#pragma unroll
        for (int ni = 0; ni < 8; ni++) {
            int col = bn + wn * 64 + ni * 8 + (lane & 3) * 2;
            if (col < N) {
                C[(size_t)row * ldC + col] = c[mi][ni][0];
                C[(size_t)row * ldC + col + 1] = c[mi][ni][1];
                C[(size_t)(row + 8) * ldC + col] = c[mi][ni][2];
                C[(size_t)(row + 8) * ldC + col + 1] = c[mi][ni][3];
            }
        }
    }
}

// ---------------- postprocess per (t, kvh) ----------------
__global__ void pp_kv_kernel(const float* __restrict__ Ccat,
                             const float* __restrict__ kmix, const float* __restrict__ vmix,
                             const float* __restrict__ k_first, const float* __restrict__ v_first,
                             const float* __restrict__ k0, const float* __restrict__ v0,
                             const float* __restrict__ knw, const float* __restrict__ cosb,
                             const float* __restrict__ sinb,
                             float* __restrict__ kf, float* __restrict__ vfout,
                             float* __restrict__ kkout) {
    int t = blockIdx.x, kvh = blockIdx.y, n = threadIdx.x;
    int idx = t * KVN_DIM + kvh * 128 + n;
    size_t cidx = (size_t)t * NCAT + kvh * 128 + n;
    __shared__ float shk[128];
    __shared__ float red[4];

    float k = Ccat[cidx + OFF_XK];
    float ss = blockReduceSum128(k * k, red);
    float kn = knw[n] * k * rsqrtf(ss * (1.0f / 128.0f) + 1e-6f);
    shk[n] = kn;
    __syncthreads();
    float rh = (n < 64) ? -shk[n + 64] : shk[n - 64];
    float c = cosb[t * 128 + n], s = sinb[t * 128 + n];
    float kr = fmaf(kn, c, rh * s);

    float kfv = kr + (k_first[idx] - kr) * sigmoidf_(k0[kvh * 128 + n] + kmix[idx]);
    float vv = Ccat[cidx + OFF_XV];
    float vfv = vv + (v_first[idx] - vv) * sigmoidf_(v0[kvh * 128 + n] + vmix[idx]);

    float nrm2 = blockReduceSum128(kfv * kfv, red);
    float denom = fmaxf(sqrtf(nrm2), 1e-12f);

    kf[idx] = kfv;
    vfout[idx] = vfv;
    kkout[idx] = kfv / denom;
}

// ---------------- postprocess per (t, h) ----------------
__global__ void pp_h_kernel(const float* __restrict__ Ccat, const float* __restrict__ wfull,
                            const float* __restrict__ afull,
                            const float* __restrict__ w0, const float* __restrict__ a0,
                            const float* __restrict__ kkbuf, const float* __restrict__ kfbuf,
                            const float* __restrict__ rnw, const float* __restrict__ cosb,
                            const float* __restrict__ sinb, const float* __restrict__ r_k,
                            float* __restrict__ rout, float* __restrict__ wdout,
                            float* __restrict__ bbout, float* __restrict__ coef,
                            float* __restrict__ c1a, float* __restrict__ c2a) {
    int t = blockIdx.x, h = blockIdx.y, n = threadIdx.x;
    int hn = h * 128 + n;
    int idx = t * HN_DIM + hn;
    __shared__ float shr[128];
    __shared__ float red[4];

    float r = Ccat[(size_t)t * NCAT + OFF_XR + hn];
    float ss = blockReduceSum128(r * r, red);
    float rn = rnw[n] * r * rsqrtf(ss * (1.0f / 128.0f) + 1e-6f);
    shr[n] = rn;
    __syncthreads();
    float rh = (n < 64) ? -shr[n + 64] : shr[n - 64];
    float c = cosb[t * 128 + n], s = sinb[t * 128 + n];
    float rr = fmaf(rn, c, rh * s);
    rout[idx] = rr;

    float z = w0[hn] + wfull[idx];
    float u = -z;
    float sp = fmaxf(u, 0.0f) + log1pf(expf(-fabsf(u)));
    float w = -sp - 0.5f;
    wdout[idx] = expf(-expf(w));

    float a = sigmoidf_(a0[hn] + afull[idx]);
    int kvidx = t * KVN_DIM + (h >> 2) * 128 + n;
    float kfv = kfbuf[kvidx];
    float bbv = kkbuf[kvidx] * a;
    bbout[idx] = bbv;

    float cs = blockReduceSum128(rr * kfv * r_k[hn], red);
    float c1s = blockReduceSum128(bbv * rr, red);
    float c2s = blockReduceSum128(kfv * rr, red);
    if (n == 0) {
        coef[t * H_NUM + h] = cs;
        c1a[t * H_NUM + h] = c1s;
        c2a[t * H_NUM + h] = c2s;
    }
}

// ---------------- the sequential scan (v2: dual-reduction + f32x2) ----------------
#define SCAN_LOAD(R, tn)                                                   \
    {                                                                      \
        size_t oH = (size_t)(tn)*HN_DIM + bH;                              \
        size_t oKV = (size_t)(tn)*KVN_DIM + bKV;                           \
        R##0 = wdec[oH];                                                   \
        R##1 = bb[oH];                                                     \
        R##2 = rr[oH];                                                     \
        R##3 = kk[oKV];                                                    \
        R##4 = kf[oKV];                                                    \
        if (tid < 16) R##5 = vf[(size_t)(tn)*KVN_DIM + vIdx];              \
        R##6 = c1a[(tn)*H_NUM + h];                                        \
        R##7 = c2a[(tn)*H_NUM + h];                                        \
    }

#define SCAN_STORE(R, s)                                                   \
    {                                                                      \
        sw[s][sidx] = R##0;                                                \
        sb[s][sidx] = R##1;                                                \
        sr[s][sidx] = R##2;                                                \
        sk[s][sidx] = R##3;                                                \
        skf[s][sidx] = R##4;                                               \
        if (tid < 16) sv[s][tid] = R##5;                                   \
        if (tid == 0) {                                                    \
            scc[s][0] = R##6;                                              \
            scc[s][1] = R##7;                                              \
        }                                                                  \
    }

#define SCAN_COMPUTE(cbuf, tt)                                                           \
    {                                                                                    \
        ulonglong2 W_[4], B_[4], K_[4], F_[4], R_[4];                                    \
        _Pragma("unroll") for (int q = 0; q < 4; q++) {                                  \
            W_[q] = *(const ulonglong2*)&sw[cbuf][jp + q * 4];                           \
            B_[q] = *(const ulonglong2*)&sb[cbuf][jp + q * 4];                           \
            K_[q] = *(const ulonglong2*)&sk[cbuf][jp + q * 4];                           \
            F_[q] = *(const ulonglong2*)&skf[cbuf][jp + q * 4];                          \
            R_[q] = *(const ulonglong2*)&sr[cbuf][jp + q * 4];                           \
        }                                                                                \
        unsigned long long wr[8];                                                        \
        _Pragma("unroll") for (int q = 0; q < 4; q++) {                                  \
            wr[2 * q] = mul2_(W_[q].x, R_[q].x);                                         \
            wr[2 * q + 1] = mul2_(W_[q].y, R_[q].y);                                     \
        }                                                                                \
        unsigned long long sA0 = mul2_(S[0], K_[0].x);                                   \
        unsigned long long sA1 = mul2_(S[1], K_[0].y);                                   \
        unsigned long long dA0 = mul2_(S[0], wr[0]);                                     \
        unsigned long long dA1 = mul2_(S[1], wr[1]);                                     \
        sA0 = fma2_(S[2], K_[1].x, sA0);                                                 \
        sA1 = fma2_(S[3], K_[1].y, sA1);                                                 \
        dA0 = fma2_(S[2], wr[2], dA0);                                                   \
        dA1 = fma2_(S[3], wr[3], dA1);                                                   \
        sA0 = fma2_(S[4], K_[2].x, sA0);                                                 \
        sA1 = fma2_(S[5], K_[2].y, sA1);                                                 \
        dA0 = fma2_(S[4], wr[4], dA0);                                                   \
        dA1 = fma2_(S[5], wr[5], dA1);                                                   \
        sA0 = fma2_(S[6], K_[3].x, sA0);                                                 \
        sA1 = fma2_(S[7], K_[3].y, sA1);                                                 \
        dA0 = fma2_(S[6], wr[6], dA0);                                                   \
        dA1 = fma2_(S[7], wr[7], dA1);                                                   \
        sA0 = add2_(sA0, sA1);                                                           \
        dA0 = add2_(dA0, dA1);                                                           \
        float2 spp = unpack2(sA0);                                                       \
        float sa = spp.x + spp.y;                                                        \
        float2 dpp = unpack2(dA0);                                                       \
        float d1s = dpp.x + dpp.y;                                                       \
        sa += __shfl_xor_sync(0xffffffffu, sa, 1);                                       \
        d1s += __shfl_xor_sync(0xffffffffu, d1s, 1);                                     \
        sa += __shfl_xor_sync(0xffffffffu, sa, 2);                                       \
        d1s += __shfl_xor_sync(0xffffffffu, d1s, 2);                                     \
        sa += __shfl_xor_sync(0xffffffffu, sa, 4);                                       \
        d1s += __shfl_xor_sync(0xffffffffu, d1s, 4);                                     \
        sa = -sa;                                                                        \
        const float v = sv[cbuf][rl];                                                    \
        float yp = fmaf(sa, scc[cbuf][0], fmaf(v, scc[cbuf][1], d1s));                   \
        if (jc == 0) y[(size_t)(tt)*HN_DIM + yIdx] = yp;                                 \
        unsigned long long sa2 = pack2(sa, sa);                                          \
        unsigned long long vv2 = pack2(v, v);                                            \
        _Pragma("unroll") for (int q = 0; q < 4; q++) {                                  \
            S[2 * q] = fma2_(S[2 * q], W_[q].x, fma2_(sa2, B_[q].x, mul2_(vv2, F_[q].x))); \
            S[2 * q + 1] =                                                               \
                fma2_(S[2 * q + 1], W_[q].y, fma2_(sa2, B_[q].y, mul2_(vv2, F_[q].y)));  \
        }                                                                                \
    }

__global__ __launch_bounds__(128) void scan_kernel(const float* __restrict__ wdec,
                                                   const float* __restrict__ bb,
                                                   const float* __restrict__ kk,
                                                   const float* __restrict__ kf,
                                                   const float* __restrict__ rr,
                                                   const float* __restrict__ vf,
                                                   const float* __restrict__ c1a,
                                                   const float* __restrict__ c2a,
                                                   float* __restrict__ y) {
    const int h = blockIdx.x;
    const int rg = blockIdx.y;
    const int tid = threadIdx.x;
    const int rl = tid >> 3;
    const int jc = tid & 7;
    const int kvh = h >> 2;
    const int jp = jc * 20;  // padded word offset of this thread's 16-float slice

    __shared__ __align__(16) float sw[2][160], sb[2][160], sk[2][160], skf[2][160], sr[2][160];
    __shared__ float sv[2][16];
    __shared__ float scc[2][2];

    const int sidx = tid + ((tid >> 4) << 2);  // padded store index
    const int bH = h * 128 + tid;
    const int bKV = kvh * 128 + tid;
    const int vIdx = kvh * 128 + rg * 16 + tid;  // only valid for tid<16
    const int yIdx = h * 128 + rg * 16 + rl;

    unsigned long long S[8];
#pragma unroll
    for (int i = 0; i < 8; i++) S[i] = 0ull;

    float A0, A1, A2, A3, A4, A5 = 0.0f, A6, A7;
    float B0, B1, B2, B3, B4, B5 = 0.0f, B6, B7;

    SCAN_LOAD(A, 0);
    SCAN_STORE(A, 0);
    SCAN_LOAD(B, 1);
    __syncthreads();

    for (int t = 0; t < T_LEN; t += 2) {
        SCAN_STORE(B, 1);
        {
            int tn = (t + 2 < T_LEN) ? t + 2 : T_LEN - 1;
            SCAN_LOAD(A, tn);
        }
        SCAN_COMPUTE(0, t);
        __syncthreads();

        SCAN_STORE(A, 0);
        {
            int tn = (t + 3 < T_LEN) ? t + 3 : T_LEN - 1;
            SCAN_LOAD(B, tn);
        }
        SCAN_COMPUTE(1, t + 1);
        __syncthreads();
    }
}

// ---------------- launch ----------------
static float* symAddrF(const void* sym) {
    void* p = nullptr;
    cudaGetSymbolAddress(&p, sym);
    return (float*)p;
}
static __nv_bfloat16* symAddrB(const void* sym) {
    void* p = nullptr;
    cudaGetSymbolAddress(&p, sym);
    return (__nv_bfloat16*)p;
}

extern "C" void kernel_launch(void* const* d_in, const int* in_sizes, int n_in,
                              void* d_out, int out_size) {
    const float* x = (const float*)d_in[0];
    const float* v_first = (const float*)d_in[1];
    const float* k_first = (const float*)d_in[2];
    const float* amask = (const float*)d_in[3];
    const float* cosb = (const float*)d_in[4];
    const float* sinb = (const float*)d_in[5];
    const float* w0 = (const float*)d_in[6];
    const float* w1 = (const float*)d_in[7];
    const float* w2 = (const float*)d_in[8];
    const float* a0 = (const float*)d_in[9];
    const float* a1 = (const float*)d_in[10];
    const float* a2 = (const float*)d_in[11];
    const float* v0 = (const float*)d_in[12];
    const float* v1 = (const float*)d_in[13];
    const float* v2 = (const float*)d_in[14];
    const float* k0 = (const float*)d_in[15];
    const float* k1 = (const float*)d_in[16];
    const float* k2 = (const float*)d_in[17];
    const float* g1 = (const float*)d_in[18];
    const float* g2 = (const float*)d_in[19];
    const float* r_k = (const float*)d_in[20];
    const float* r_norm_w = (const float*)d_in[21];
    const float* k_norm_w = (const float*)d_in[22];
    const float* W_r = (const float*)d_in[23];
    const float* W_k = (const float*)d_in[24];
    const float* W_v = (const float*)d_in[25];
    const float* W_o = (const float*)d_in[26];
    float* out = (float*)d_out;

    float* Ccat = symAddrF(g_Ccat);
    float* wfull = symAddrF(g_wfull);
    float* afull = symAddrF(g_afull);
    float* gfull = symAddrF(g_gfull);
    float* vmix = symAddrF(g_vmix);
    float* kmix = symAddrF(g_kmix);
    float* rrb = symAddrF(g_rr);
    float* kf = symAddrF(g_kf);
    float* vf = symAddrF(g_vf);
    float* kkb = symAddrF(g_kk);
    float* wd = symAddrF(g_wd);
    float* bbb = symAddrF(g_bb);
    float* coef = symAddrF(g_coef);
    float* c1a = symAddrF(g_c1);
    float* c2a = symAddrF(g_c2);
    float* yb = symAddrF(g_y);
    __nv_bfloat16* Ap = symAddrB(g_Ap);
    __nv_bfloat16* Bp = symAddrB(g_Bp);

    // ---- stage 1 ----
    const int NTC2 = T_LEN * C_DIM / 2;
    splitAmask_kernel<<<(NTC2 + 255) / 256, 256>>>(x, amask, Ap, NTC2);

    const int NB2 = T_LEN * NCAT / 2;
    splitBcat_kernel<<<(NB2 + 255) / 256, 256>>>(W_r, W_k, W_v, w1, a1, v1, k1, g1, Bp, NB2);

    {
        dim3 grid((NCAT + 127) / 128, 2048 / 128);
        bf16_gemm_kernel<<<grid, 256>>>(Ap, Bp, Ccat, 2048, NCAT, 6144, NCAT, NCAT);
    }

    // ---- fused activations + stage-2 A splits ----
    const int NMIDS2 = T_LEN * NMID / 2;
    splitMids_kernel<<<(NMIDS2 + 255) / 256, 256>>>(Ccat, Ap, NMIDS2);

    // ---- stage 2: LoRA expansions ----
    auto gemm2 = [&](size_t aBase, int K, const float* B, float* C, int N) {
        int n2 = K * N / 2;
        splitB_kernel<<<(n2 + 255) / 256, 256>>>(B, Bp, K, N, N, 0, n2);
        dim3 grid((N + 127) / 128, 2048 / 128);
        bf16_gemm_kernel<<<grid, 256>>>(Ap + aBase, Bp, C, 2048, N, 3 * K, N, N);
    };
    gemm2(APW_BASE, 160, w2, wfull, 2048);
    gemm2(APA_BASE, 96, a2, afull, 2048);
    gemm2(APG_BASE, 160, g2, gfull, 2048);
    gemm2(APV_BASE, 64, v2, vmix, 512);
    gemm2(APK_BASE, 64, k2, kmix, 512);

    // ---- postprocess ----
    pp_kv_kernel<<<dim3(T_LEN, KVH_NUM), 128>>>(Ccat, kmix, vmix, k_first, v_first,
                                                k0, v0, k_norm_w, cosb, sinb,
                                                kf, vf, kkb);
    pp_h_kernel<<<dim3(T_LEN, H_NUM), 128>>>(Ccat, wfull, afull, w0, a0, kkb, kf,
                                             r_norm_w, cosb, sinb, r_k,
                                             rrb, wd, bbb, coef, c1a, c2a);

    // ---- sequential scan ----
    scan_kernel<<<dim3(H_NUM, 8), 128>>>(wd, bbb, kkb, kf, rrb, vf, c1a, c2a, yb);

    // ---- fused merge + final A split ----
    const int NHN2 = T_LEN * HN_DIM / 2;
    mergeSplitA_kernel<<<(NHN2 + 255) / 256, 256>>>(yb, coef, vf, gfull, Ap, NHN2);

    // ---- final projection ----
    {
        int n2 = 2048 * 2048 / 2;
        splitB_kernel<<<(n2 + 255) / 256, 256>>>(W_o, Bp, 2048, 2048, 2048, 0, n2);
        dim3 grid(2048 / 128, 2048 / 128);
        bf16_gemm_kernel<<<grid, 256>>>(Ap, Bp, out, 2048, 2048, 6144, 2048, 2048);
    }
}

// round 7
// speedup vs baseline: 1.0065x; 1.0065x over previous
#include <cuda_runtime.h>
#include <cuda_bf16.h>
#include <cstdint>

#define T_LEN 2048
#define C_DIM 2048
#define H_NUM 16
#define N_DIM 128
#define KVH_NUM 4
#define HN_DIM 2048
#define KVN_DIM 512

// fused stage-1 output column offsets
#define OFF_XR 0
#define OFF_XK 2048
#define OFF_XV 2560
#define OFF_TW 3072
#define OFF_TA 3232
#define OFF_TV 3328
#define OFF_TK 3392
#define OFF_TG 3456
#define NCAT 3616
#define NMID 544

// stage-2 A' regions inside g_Ap (element offsets)
#define APW_BASE 0
#define APA_BASE 983040
#define APG_BASE 1572864
#define APV_BASE 2555904
#define APK_BASE 2949120

// ---------------- scratch ----------------
__device__ float g_Ccat[(size_t)T_LEN * NCAT];
__device__ float g_wfull[T_LEN * HN_DIM];
__device__ float g_afull[T_LEN * HN_DIM];
__device__ float g_gfull[T_LEN * HN_DIM];
__device__ float g_vmix[T_LEN * KVN_DIM];
__device__ float g_kmix[T_LEN * KVN_DIM];
__device__ float g_rr[T_LEN * HN_DIM];
__device__ float g_kf[T_LEN * KVN_DIM];
__device__ float g_vf[T_LEN * KVN_DIM];
__device__ float g_kk[T_LEN * KVN_DIM];
__device__ float g_wd[T_LEN * HN_DIM];
__device__ float g_bb[T_LEN * HN_DIM];
__device__ float g_coef[T_LEN * H_NUM];
__device__ float2 g_c12[T_LEN * H_NUM];
__device__ float g_y[T_LEN * HN_DIM];

__device__ __nv_bfloat16 g_Ap[(size_t)2048 * 3 * 2048];
__device__ __nv_bfloat16 g_Bp[(size_t)3 * 2048 * NCAT];

// ---------------- helpers ----------------
__device__ __forceinline__ float sigmoidf_(float x) { return 1.0f / (1.0f + expf(-x)); }

__device__ __forceinline__ float blockReduceSum128(float v, float* red) {
#pragma unroll
    for (int m = 16; m > 0; m >>= 1) v += __shfl_xor_sync(0xffffffffu, v, m);
    __syncthreads();
    if ((threadIdx.x & 31) == 0) red[threadIdx.x >> 5] = v;
    __syncthreads();
    return red[0] + red[1] + red[2] + red[3];
}

// fused 3-value block reduce (one barrier pair)
__device__ __forceinline__ void blockReduceSum3(float& a, float& b, float& c,
                                                float (*red)[3]) {
#pragma unroll
    for (int m = 16; m > 0; m >>= 1) {
        a += __shfl_xor_sync(0xffffffffu, a, m);
        b += __shfl_xor_sync(0xffffffffu, b, m);
        c += __shfl_xor_sync(0xffffffffu, c, m);
    }
    __syncthreads();
    if ((threadIdx.x & 31) == 0) {
        int w = threadIdx.x >> 5;
        red[w][0] = a;
        red[w][1] = b;
        red[w][2] = c;
    }
    __syncthreads();
    a = red[0][0] + red[1][0] + red[2][0] + red[3][0];
    b = red[0][1] + red[1][1] + red[2][1] + red[3][1];
    c = red[0][2] + red[1][2] + red[2][2] + red[3][2];
}

// packed f32x2 ops (sm_103a)
typedef unsigned long long ull;
__device__ __forceinline__ ull pack2(float x, float y) {
    ull r;
    asm("mov.b64 %0, {%1, %2};" : "=l"(r) : "f"(x), "f"(y));
    return r;
}
__device__ __forceinline__ float2 unpack2(ull v) {
    float x, y;
    asm("mov.b64 {%0, %1}, %2;" : "=f"(x), "=f"(y) : "l"(v));
    return make_float2(x, y);
}
__device__ __forceinline__ ull fma2_(ull a, ull b, ull c) {
    ull d;
    asm("fma.rn.f32x2 %0, %1, %2, %3;" : "=l"(d) : "l"(a), "l"(b), "l"(c));
    return d;
}
__device__ __forceinline__ ull mul2_(ull a, ull b) {
    ull d;
    asm("mul.rn.f32x2 %0, %1, %2;" : "=l"(d) : "l"(a), "l"(b));
    return d;
}

__device__ __forceinline__ uint32_t packsplit_hi(float a, float b) {
    __nv_bfloat162 h = __floats2bfloat162_rn(a, b);
    return *(uint32_t*)&h;
}
__device__ __forceinline__ uint32_t packsplit_lo(float a, float b, uint32_t hipack) {
    __nv_bfloat162* hp = (__nv_bfloat162*)&hipack;
    float ra = a - __bfloat162float(hp->x);
    float rb = b - __bfloat162float(hp->y);
    __nv_bfloat162 l = __floats2bfloat162_rn(ra, rb);
    return *(uint32_t*)&l;
}

// ---------------- split conversions ----------------
__global__ void splitAmask_kernel(const float* __restrict__ x, const float* __restrict__ mask,
                                  __nv_bfloat16* __restrict__ Ap, int n2) {
    int i = blockIdx.x * blockDim.x + threadIdx.x;
    if (i >= n2) return;
    int i2 = i * 2;
    int r = i2 >> 11, c = i2 & 2047;
    float2 xv = *(const float2*)&x[i2];
    float m = mask[r];
    float v0 = xv.x * m, v1 = xv.y * m;
    uint32_t hi = packsplit_hi(v0, v1);
    uint32_t lo = packsplit_lo(v0, v1, hi);
    size_t base = (size_t)r * 6144 + c;
    *(uint32_t*)&Ap[base] = hi;
    *(uint32_t*)&Ap[base + 2048] = lo;
    *(uint32_t*)&Ap[base + 4096] = hi;
}

__global__ void splitBcat_kernel(const float* __restrict__ W_r, const float* __restrict__ W_k,
                                 const float* __restrict__ W_v, const float* __restrict__ w1,
                                 const float* __restrict__ a1, const float* __restrict__ v1,
                                 const float* __restrict__ k1, const float* __restrict__ g1,
                                 __nv_bfloat16* __restrict__ Bp, int n2) {
    int i = blockIdx.x * blockDim.x + threadIdx.x;
    if (i >= n2) return;
    int i2 = i * 2;
    int r = i2 / NCAT, c = i2 - r * NCAT;
    const float* src;
    int off, ncols;
    if (c < 2048) { src = W_r; off = OFF_XR; ncols = 2048; }
    else if (c < 2560) { src = W_k; off = OFF_XK; ncols = 512; }
    else if (c < 3072) { src = W_v; off = OFF_XV; ncols = 512; }
    else if (c < 3232) { src = w1; off = OFF_TW; ncols = 160; }
    else if (c < 3328) { src = a1; off = OFF_TA; ncols = 96; }
    else if (c < 3392) { src = v1; off = OFF_TV; ncols = 64; }
    else if (c < 3456) { src = k1; off = OFF_TK; ncols = 64; }
    else { src = g1; off = OFF_TG; ncols = 160; }
    float2 xv = *(const float2*)&src[(size_t)r * ncols + (c - off)];
    uint32_t hi = packsplit_hi(xv.x, xv.y);
    uint32_t lo = packsplit_lo(xv.x, xv.y, hi);
    size_t base = (size_t)r * NCAT + c;
    *(uint32_t*)&Bp[base] = hi;
    *(uint32_t*)&Bp[base + (size_t)2048 * NCAT] = hi;
    *(uint32_t*)&Bp[base + (size_t)4096 * NCAT] = lo;
}

__global__ void splitB_kernel(const float* __restrict__ B, __nv_bfloat16* __restrict__ Bp,
                              int K, int Ncols, int ldB, int colOff, int n2) {
    int i = blockIdx.x * blockDim.x + threadIdx.x;
    if (i >= n2) return;
    int i2 = i * 2;
    int r = i2 / Ncols, c = i2 - r * Ncols;
    float2 xv = *(const float2*)&B[i2];
    uint32_t hi = packsplit_hi(xv.x, xv.y);
    uint32_t lo = packsplit_lo(xv.x, xv.y, hi);
    size_t base = (size_t)r * ldB + colOff + c;
    *(uint32_t*)&Bp[base] = hi;
    *(uint32_t*)&Bp[base + (size_t)K * ldB] = hi;
    *(uint32_t*)&Bp[base + (size_t)2 * K * ldB] = lo;
}

// ---------------- fused act + stage-2 A-split from Ccat ----------------
__global__ void splitMids_kernel(const float* __restrict__ Ccat, __nv_bfloat16* __restrict__ Ap,
                                 int n2) {
    int i = blockIdx.x * blockDim.x + threadIdx.x;
    if (i >= n2) return;
    int i2 = i * 2;
    int t = i2 / NMID, c = i2 - t * NMID;
    const float* src = &Ccat[(size_t)t * NCAT + OFF_TW];
    float v0 = src[c], v1 = src[c + 1];
    int K, lc;
    size_t base;
    if (c < 160) {
        v0 = tanhf(v0); v1 = tanhf(v1);
        K = 160; base = APW_BASE; lc = c;
    } else if (c < 256) {
        K = 96; base = APA_BASE; lc = c - 160;
    } else if (c < 320) {
        K = 64; base = APV_BASE; lc = c - 256;
    } else if (c < 384) {
        K = 64; base = APK_BASE; lc = c - 320;
    } else {
        v0 = sigmoidf_(v0); v1 = sigmoidf_(v1);
        K = 160; base = APG_BASE; lc = c - 384;
    }
    uint32_t hi = packsplit_hi(v0, v1);
    uint32_t lo = packsplit_lo(v0, v1, hi);
    size_t off = base + (size_t)t * (3 * K) + lc;
    *(uint32_t*)&Ap[off] = hi;
    *(uint32_t*)&Ap[off + K] = lo;
    *(uint32_t*)&Ap[off + 2 * K] = hi;
}

// ---------------- fused merge + final A-split ----------------
__global__ void mergeSplitA_kernel(const float* __restrict__ y, const float* __restrict__ coef,
                                   const float* __restrict__ vf, const float* __restrict__ gbuf,
                                   __nv_bfloat16* __restrict__ Ap, int n2) {
    int i = blockIdx.x * blockDim.x + threadIdx.x;
    if (i >= n2) return;
    int i2 = i * 2;
    int t = i2 >> 11, hn = i2 & 2047;
    int h = hn >> 7, nn = hn & 127;
    float cf = coef[t * H_NUM + h];
    const float* vp = &vf[t * KVN_DIM + (h >> 2) * 128 + nn];
    float2 yv = *(const float2*)&y[i2];
    float2 gv = *(const float2*)&gbuf[i2];
    float v0 = (yv.x + cf * vp[0]) * gv.x;
    float v1 = (yv.y + cf * vp[1]) * gv.y;
    uint32_t hi = packsplit_hi(v0, v1);
    uint32_t lo = packsplit_lo(v0, v1, hi);
    size_t base = (size_t)t * 6144 + hn;
    *(uint32_t*)&Ap[base] = hi;
    *(uint32_t*)&Ap[base + 2048] = lo;
    *(uint32_t*)&Ap[base + 4096] = hi;
}

// ---------------- bf16 tensor-core GEMM, 3-stage cp.async pipeline ----------------
#define LDA_S 40
#define LDB_S 136
#define NSTAGE 3

__global__ __launch_bounds__(256) void bf16_gemm_kernel(
    const __nv_bfloat16* __restrict__ A, const __nv_bfloat16* __restrict__ B,
    float* __restrict__ C, int M, int N, int K3, int ldB, int ldC) {
    __shared__ __align__(16) __nv_bfloat16 As[NSTAGE][128 * LDA_S];
    __shared__ __align__(16) __nv_bfloat16 Bs[NSTAGE][32 * LDB_S];

    const int tid = threadIdx.x;
    const int bm = blockIdx.y * 128;
    const int bn = blockIdx.x * 128;
    const int warp = tid >> 5;
    const int lane = tid & 31;
    const int wm = warp & 3;
    const int wn = warp >> 2;

    const int ar = tid >> 2;
    const int ac = (tid & 3) * 8;
    const int br = tid >> 4;
    const int bc = (tid & 15) * 8;
    const int bsz = ((bn + bc) < N) ? 16 : 0;

    float c[2][8][4];
#pragma unroll
    for (int mi = 0; mi < 2; mi++)
#pragma unroll
        for (int ni = 0; ni < 8; ni++)
#pragma unroll
            for (int q = 0; q < 4; q++) c[mi][ni][q] = 0.0f;

    const int KT = K3 >> 5;

    auto load_stage = [&](int st, int kt) {
        int k0 = kt * 32;
#pragma unroll
        for (int it = 0; it < 2; it++) {
            const __nv_bfloat16* src = A + (size_t)(bm + ar + it * 64) * K3 + k0 + ac;
            uint32_t dst = (uint32_t)__cvta_generic_to_shared(&As[st][(ar + it * 64) * LDA_S + ac]);
            asm volatile("cp.async.ca.shared.global [%0], [%1], 16;\n" ::"r"(dst), "l"(src));
        }
#pragma unroll
        for (int it = 0; it < 2; it++) {
            const __nv_bfloat16* src = B + (size_t)(k0 + br + it * 16) * ldB + bn + bc;
            uint32_t dst = (uint32_t)__cvta_generic_to_shared(&Bs[st][(br + it * 16) * LDB_S + bc]);
            asm volatile("cp.async.ca.shared.global [%0], [%1], 16, %2;\n" ::"r"(dst), "l"(src),
                         "r"(bsz));
        }
        asm volatile("cp.async.commit_group;\n");
    };

    auto compute_stage = [&](int st) {
#pragma unroll
        for (int kk = 0; kk < 32; kk += 16) {
            uint32_t af[2][4];
#pragma unroll
            for (int mi = 0; mi < 2; mi++) {
                uint32_t addr = (uint32_t)__cvta_generic_to_shared(
                    &As[st][(wm * 32 + mi * 16 + (lane & 15)) * LDA_S + kk + (lane >> 4) * 8]);
                asm volatile("ldmatrix.sync.aligned.m8n8.x4.shared.b16 {%0,%1,%2,%3}, [%4];\n"
                             : "=r"(af[mi][0]), "=r"(af[mi][1]), "=r"(af[mi][2]), "=r"(af[mi][3])
                             : "r"(addr));
            }
            uint32_t bfr[8][2];
#pragma unroll
            for (int p = 0; p < 4; p++) {
                uint32_t addr = (uint32_t)__cvta_generic_to_shared(
                    &Bs[st][(kk + (lane & 15)) * LDB_S + wn * 64 + p * 16 + (lane >> 4) * 8]);
                uint32_t b0, b1, b2, b3;
                asm volatile("ldmatrix.sync.aligned.m8n8.x4.trans.shared.b16 {%0,%1,%2,%3}, [%4];\n"
                             : "=r"(b0), "=r"(b1), "=r"(b2), "=r"(b3)
                             : "r"(addr));
                bfr[p * 2][0] = b0;
                bfr[p * 2][1] = b1;
                bfr[p * 2 + 1][0] = b2;
                bfr[p * 2 + 1][1] = b3;
            }
#pragma unroll
            for (int mi = 0; mi < 2; mi++)
#pragma unroll
                for (int ni = 0; ni < 8; ni++) {
                    asm volatile(
                        "mma.sync.aligned.m16n8k16.row.col.f32.bf16.bf16.f32 "
                        "{%0,%1,%2,%3}, {%4,%5,%6,%7}, {%8,%9}, {%0,%1,%2,%3};\n"
                        : "+f"(c[mi][ni][0]), "+f"(c[mi][ni][1]), "+f"(c[mi][ni][2]),
                          "+f"(c[mi][ni][3])
                        : "r"(af[mi][0]), "r"(af[mi][1]), "r"(af[mi][2]), "r"(af[mi][3]),
                          "r"(bfr[ni][0]), "r"(bfr[ni][1]));
                }
        }
    };

    load_stage(0, 0);
    if (KT > 1) load_stage(1, 1);
    for (int kt = 0; kt < KT; kt++) {
        if (kt + 2 < KT) {
            load_stage((kt + 2) % NSTAGE, kt + 2);
            asm volatile("cp.async.wait_group 2;\n");
        } else if (kt + 1 < KT) {
            asm volatile("cp.async.wait_group 1;\n");
        } else {
            asm volatile("cp.async.wait_group 0;\n");
        }
        __syncthreads();
        compute_stage(kt % NSTAGE);
        __syncthreads();
    }

#pragma unroll
    for (int mi = 0; mi < 2; mi++) {
        int row = bm + wm * 32 + mi * 16 + (lane >> 2);
#pragma unroll
        for (int ni = 0; ni < 8; ni++) {
            int col = bn + wn * 64 + ni * 8 + (lane & 3) * 2;
            if (col < N) {
                C[(size_t)row * ldC + col] = c[mi][ni][0];
                C[(size_t)row * ldC + col + 1] = c[mi][ni][1];
                C[(size_t)(row + 8) * ldC + col] = c[mi][ni][2];
                C[(size_t)(row + 8) * ldC + col + 1] = c[mi][ni][3];
            }
        }
    }
}

// ---------------- postprocess per (t, kvh) ----------------
__global__ void pp_kv_kernel(const float* __restrict__ Ccat,
                             const float* __restrict__ kmix, const float* __restrict__ vmix,
                             const float* __restrict__ k_first, const float* __restrict__ v_first,
                             const float* __restrict__ k0, const float* __restrict__ v0,
                             const float* __restrict__ knw, const float* __restrict__ cosb,
                             const float* __restrict__ sinb,
                             float* __restrict__ kf, float* __restrict__ vfout,
                             float* __restrict__ kkout) {
    int t = blockIdx.x, kvh = blockIdx.y, n = threadIdx.x;
    int idx = t * KVN_DIM + kvh * 128 + n;
    size_t cidx = (size_t)t * NCAT + kvh * 128 + n;
    __shared__ float shk[128];
    __shared__ float red[4];

    float k = Ccat[cidx + OFF_XK];
    float ss = blockReduceSum128(k * k, red);
    float kn = knw[n] * k * rsqrtf(ss * (1.0f / 128.0f) + 1e-6f);
    shk[n] = kn;
    __syncthreads();
    float rh = (n < 64) ? -shk[n + 64] : shk[n - 64];
    float c = cosb[t * 128 + n], s = sinb[t * 128 + n];
    float kr = fmaf(kn, c, rh * s);

    float kfv = kr + (k_first[idx] - kr) * sigmoidf_(k0[kvh * 128 + n] + kmix[idx]);
    float vv = Ccat[cidx + OFF_XV];
    float vfv = vv + (v_first[idx] - vv) * sigmoidf_(v0[kvh * 128 + n] + vmix[idx]);

    float nrm2 = blockReduceSum128(kfv * kfv, red);
    float denom = fmaxf(sqrtf(nrm2), 1e-12f);

    kf[idx] = kfv;
    vfout[idx] = vfv;
    kkout[idx] = kfv / denom;
}

// ---------------- postprocess per (t, h) ----------------
__global__ void pp_h_kernel(const float* __restrict__ Ccat, const float* __restrict__ wfull,
                            const float* __restrict__ afull,
                            const float* __restrict__ w0, const float* __restrict__ a0,
                            const float* __restrict__ kkbuf, const float* __restrict__ kfbuf,
                            const float* __restrict__ rnw, const float* __restrict__ cosb,
                            const float* __restrict__ sinb, const float* __restrict__ r_k,
                            float* __restrict__ rout, float* __restrict__ wdout,
                            float* __restrict__ bbout, float* __restrict__ coef,
                            float2* __restrict__ c12) {
    int t = blockIdx.x, h = blockIdx.y, n = threadIdx.x;
    int hn = h * 128 + n;
    int idx = t * HN_DIM + hn;
    __shared__ float shr[128];
    __shared__ float red[4];
    __shared__ float red3[4][3];

    float r = Ccat[(size_t)t * NCAT + OFF_XR + hn];
    float ss = blockReduceSum128(r * r, red);
    float rn = rnw[n] * r * rsqrtf(ss * (1.0f / 128.0f) + 1e-6f);
    shr[n] = rn;
    __syncthreads();
    float rh = (n < 64) ? -shr[n + 64] : shr[n - 64];
    float c = cosb[t * 128 + n], s = sinb[t * 128 + n];
    float rr = fmaf(rn, c, rh * s);
    rout[idx] = rr;

    float z = w0[hn] + wfull[idx];
    float u = -z;
    float sp = fmaxf(u, 0.0f) + log1pf(expf(-fabsf(u)));
    float w = -sp - 0.5f;
    wdout[idx] = expf(-expf(w));

    float a = sigmoidf_(a0[hn] + afull[idx]);
    int kvidx = t * KVN_DIM + (h >> 2) * 128 + n;
    float kfv = kfbuf[kvidx];
    float bbv = kkbuf[kvidx] * a;
    bbout[idx] = bbv;

    float p0 = rr * kfv * r_k[hn];
    float p1 = bbv * rr;
    float p2 = kfv * rr;
    blockReduceSum3(p0, p1, p2, red3);
    if (n == 0) {
        coef[t * H_NUM + h] = p0;
        c12[t * H_NUM + h] = make_float2(p1, p2);
    }
}

// ---------------- the sequential scan (v3: warp-autonomous, no barriers/smem) ----------------
// grid (16 h, 32 rowgroups), 32 threads/block = 1 warp. Each warp owns 4 rows of S;
// lane owns a 4-wide j-slice. Reductions via 5-round shfl butterflies (sa + d1).
__global__ __launch_bounds__(32) void scan_kernel(const float* __restrict__ wdec,
                                                  const float* __restrict__ bb,
                                                  const float* __restrict__ kk,
                                                  const float* __restrict__ kf,
                                                  const float* __restrict__ rr,
                                                  const float* __restrict__ vf,
                                                  const float2* __restrict__ c12,
                                                  float* __restrict__ y) {
    const int h = blockIdx.x;
    const int rg = blockIdx.y;
    const int lane = threadIdx.x;
    const int kvh = h >> 2;

    const int hoff = h * 128 + lane * 4;
    const int koff = kvh * 128 + lane * 4;
    const int voff = kvh * 128 + rg * 4;
    float* py = y + h * 128 + rg * 4;

    ull S2[4][2];
#pragma unroll
    for (int i = 0; i < 4; i++) { S2[i][0] = 0ull; S2[i][1] = 0ull; }

    // current-step data
    float4 w4 = *(const float4*)&wdec[hoff];
    float4 b4 = *(const float4*)&bb[hoff];
    float4 r4 = *(const float4*)&rr[hoff];
    float4 k4 = *(const float4*)&kk[koff];
    float4 f4 = *(const float4*)&kf[koff];
    float4 v4 = *(const float4*)&vf[voff];
    float2 cc = c12[h];

    for (int t = 0; t < T_LEN; t++) {
        // prefetch t+1
        int tn = (t + 1 < T_LEN) ? (t + 1) : (T_LEN - 1);
        size_t oH = (size_t)tn * HN_DIM;
        size_t oKV = (size_t)tn * KVN_DIM;
        float4 nw = *(const float4*)&wdec[oH + hoff];
        float4 nb = *(const float4*)&bb[oH + hoff];
        float4 nr = *(const float4*)&rr[oH + hoff];
        float4 nk = *(const float4*)&kk[oKV + koff];
        float4 nf = *(const float4*)&kf[oKV + koff];
        float4 nv = *(const float4*)&vf[oKV + voff];
        float2 ncc = c12[tn * H_NUM + h];

        // pack halves
        ull wA = pack2(w4.x, w4.y), wB = pack2(w4.z, w4.w);
        ull bA = pack2(b4.x, b4.y), bB = pack2(b4.z, b4.w);
        ull kA = pack2(k4.x, k4.y), kB = pack2(k4.z, k4.w);
        ull fA = pack2(f4.x, f4.y), fB = pack2(f4.z, f4.w);
        ull wrA = pack2(w4.x * r4.x, w4.y * r4.y);
        ull wrB = pack2(w4.z * r4.z, w4.w * r4.w);

        // per-row partial dots: sa_i = S_i . kk ; d1_i = S_i . (w*r)
        float sa[4], d1[4];
#pragma unroll
        for (int i = 0; i < 4; i++) {
            ull sdp = fma2_(S2[i][1], kB, mul2_(S2[i][0], kA));
            float2 su = unpack2(sdp);
            sa[i] = su.x + su.y;
            ull ddp = fma2_(S2[i][1], wrB, mul2_(S2[i][0], wrA));
            float2 du = unpack2(ddp);
            d1[i] = du.x + du.y;
        }

        // 5-round butterfly over 32 lanes, 8 values pipelined per round
#pragma unroll
        for (int m = 16; m > 0; m >>= 1) {
            sa[0] += __shfl_xor_sync(0xffffffffu, sa[0], m);
            sa[1] += __shfl_xor_sync(0xffffffffu, sa[1], m);
            sa[2] += __shfl_xor_sync(0xffffffffu, sa[2], m);
            sa[3] += __shfl_xor_sync(0xffffffffu, sa[3], m);
            d1[0] += __shfl_xor_sync(0xffffffffu, d1[0], m);
            d1[1] += __shfl_xor_sync(0xffffffffu, d1[1], m);
            d1[2] += __shfl_xor_sync(0xffffffffu, d1[2], m);
            d1[3] += __shfl_xor_sync(0xffffffffu, d1[3], m);
        }
#pragma unroll
        for (int i = 0; i < 4; i++) sa[i] = -sa[i];

        // y_i = d1_i + sa_i*c1 + v_i*c2 ; lane 0 stores float4
        if (lane == 0) {
            float4 yo;
            yo.x = fmaf(sa[0], cc.x, fmaf(v4.x, cc.y, d1[0]));
            yo.y = fmaf(sa[1], cc.x, fmaf(v4.y, cc.y, d1[1]));
            yo.z = fmaf(sa[2], cc.x, fmaf(v4.z, cc.y, d1[2]));
            yo.w = fmaf(sa[3], cc.x, fmaf(v4.w, cc.y, d1[3]));
            *(float4*)&py[(size_t)t * HN_DIM] = yo;
        }

        // S update: S_i = S_i*w + sa_i*b + v_i*kf
        const float vv[4] = {v4.x, v4.y, v4.z, v4.w};
#pragma unroll
        for (int i = 0; i < 4; i++) {
            ull sai = pack2(sa[i], sa[i]);
            ull vvi = pack2(vv[i], vv[i]);
            S2[i][0] = fma2_(S2[i][0], wA, fma2_(sai, bA, mul2_(vvi, fA)));
            S2[i][1] = fma2_(S2[i][1], wB, fma2_(sai, bB, mul2_(vvi, fB)));
        }

        // rotate
        w4 = nw; b4 = nb; r4 = nr; k4 = nk; f4 = nf; v4 = nv; cc = ncc;
    }
}

// ---------------- launch ----------------
static float* symAddrF(const void* sym) {
    void* p = nullptr;
    cudaGetSymbolAddress(&p, sym);
    return (float*)p;
}
static float2* symAddrF2(const void* sym) {
    void* p = nullptr;
    cudaGetSymbolAddress(&p, sym);
    return (float2*)p;
}
static __nv_bfloat16* symAddrB(const void* sym) {
    void* p = nullptr;
    cudaGetSymbolAddress(&p, sym);
    return (__nv_bfloat16*)p;
}

extern "C" void kernel_launch(void* const* d_in, const int* in_sizes, int n_in,
                              void* d_out, int out_size) {
    const float* x = (const float*)d_in[0];
    const float* v_first = (const float*)d_in[1];
    const float* k_first = (const float*)d_in[2];
    const float* amask = (const float*)d_in[3];
    const float* cosb = (const float*)d_in[4];
    const float* sinb = (const float*)d_in[5];
    const float* w0 = (const float*)d_in[6];
    const float* w1 = (const float*)d_in[7];
    const float* w2 = (const float*)d_in[8];
    const float* a0 = (const float*)d_in[9];
    const float* a1 = (const float*)d_in[10];
    const float* a2 = (const float*)d_in[11];
    const float* v0 = (const float*)d_in[12];
    const float* v1 = (const float*)d_in[13];
    const float* v2 = (const float*)d_in[14];
    const float* k0 = (const float*)d_in[15];
    const float* k1 = (const float*)d_in[16];
    const float* k2 = (const float*)d_in[17];
    const float* g1 = (const float*)d_in[18];
    const float* g2 = (const float*)d_in[19];
    const float* r_k = (const float*)d_in[20];
    const float* r_norm_w = (const float*)d_in[21];
    const float* k_norm_w = (const float*)d_in[22];
    const float* W_r = (const float*)d_in[23];
    const float* W_k = (const float*)d_in[24];
    const float* W_v = (const float*)d_in[25];
    const float* W_o = (const float*)d_in[26];
    float* out = (float*)d_out;

    float* Ccat = symAddrF(g_Ccat);
    float* wfull = symAddrF(g_wfull);
    float* afull = symAddrF(g_afull);
    float* gfull = symAddrF(g_gfull);
    float* vmix = symAddrF(g_vmix);
    float* kmix = symAddrF(g_kmix);
    float* rrb = symAddrF(g_rr);
    float* kf = symAddrF(g_kf);
    float* vf = symAddrF(g_vf);
    float* kkb = symAddrF(g_kk);
    float* wd = symAddrF(g_wd);
    float* bbb = symAddrF(g_bb);
    float* coef = symAddrF(g_coef);
    float2* c12 = symAddrF2(g_c12);
    float* yb = symAddrF(g_y);
    __nv_bfloat16* Ap = symAddrB(g_Ap);
    __nv_bfloat16* Bp = symAddrB(g_Bp);

    // ---- stage 1 ----
    const int NTC2 = T_LEN * C_DIM / 2;
    splitAmask_kernel<<<(NTC2 + 255) / 256, 256>>>(x, amask, Ap, NTC2);

    const int NB2 = T_LEN * NCAT / 2;
    splitBcat_kernel<<<(NB2 + 255) / 256, 256>>>(W_r, W_k, W_v, w1, a1, v1, k1, g1, Bp, NB2);

    {
        dim3 grid((NCAT + 127) / 128, 2048 / 128);
        bf16_gemm_kernel<<<grid, 256>>>(Ap, Bp, Ccat, 2048, NCAT, 6144, NCAT, NCAT);
    }

    // ---- fused activations + stage-2 A splits ----
    const int NMIDS2 = T_LEN * NMID / 2;
    splitMids_kernel<<<(NMIDS2 + 255) / 256, 256>>>(Ccat, Ap, NMIDS2);

    // ---- stage 2: LoRA expansions ----
    auto gemm2 = [&](size_t aBase, int K, const float* B, float* C, int N) {
        int n2 = K * N / 2;
        splitB_kernel<<<(n2 + 255) / 256, 256>>>(B, Bp, K, N, N, 0, n2);
        dim3 grid((N + 127) / 128, 2048 / 128);
        bf16_gemm_kernel<<<grid, 256>>>(Ap + aBase, Bp, C, 2048, N, 3 * K, N, N);
    };
    gemm2(APW_BASE, 160, w2, wfull, 2048);
    gemm2(APA_BASE, 96, a2, afull, 2048);
    gemm2(APG_BASE, 160, g2, gfull, 2048);
    gemm2(APV_BASE, 64, v2, vmix, 512);
    gemm2(APK_BASE, 64, k2, kmix, 512);

    // ---- postprocess ----
    pp_kv_kernel<<<dim3(T_LEN, KVH_NUM), 128>>>(Ccat, kmix, vmix, k_first, v_first,
                                                k0, v0, k_norm_w, cosb, sinb,
                                                kf, vf, kkb);
    pp_h_kernel<<<dim3(T_LEN, H_NUM), 128>>>(Ccat, wfull, afull, w0, a0, kkb, kf,
                                             r_norm_w, cosb, sinb, r_k,
                                             rrb, wd, bbb, coef, c12);

    // ---- sequential scan: 512 independent warps ----
    scan_kernel<<<dim3(H_NUM, 32), 32>>>(wd, bbb, kkb, kf, rrb, vf, c12, yb);

    // ---- fused merge + final A split ----
    const int NHN2 = T_LEN * HN_DIM / 2;
    mergeSplitA_kernel<<<(NHN2 + 255) / 256, 256>>>(yb, coef, vf, gfull, Ap, NHN2);

    // ---- final projection ----
    {
        int n2 = 2048 * 2048 / 2;
        splitB_kernel<<<(n2 + 255) / 256, 256>>>(W_o, Bp, 2048, 2048, 2048, 0, n2);
        dim3 grid(2048 / 128, 2048 / 128);
        bf16_gemm_kernel<<<grid, 256>>>(Ap, Bp, out, 2048, 2048, 6144, 2048, 2048);
    }
}

// round 8
// speedup vs baseline: 1.6247x; 1.6142x over previous
#include <cuda_runtime.h>
#include <cuda_bf16.h>
#include <cstdint>

#define T_LEN 2048
#define C_DIM 2048
#define H_NUM 16
#define N_DIM 128
#define KVH_NUM 4
#define HN_DIM 2048
#define KVN_DIM 512

// fused stage-1 output column offsets
#define OFF_XR 0
#define OFF_XK 2048
#define OFF_XV 2560
#define OFF_TW 3072
#define OFF_TA 3232
#define OFF_TV 3328
#define OFF_TK 3392
#define OFF_TG 3456
#define NCAT 3616
#define NMID 544

// stage-2 A' regions inside g_Ap (element offsets)
#define APW_BASE 0
#define APA_BASE 983040
#define APG_BASE 1572864
#define APV_BASE 2555904
#define APK_BASE 2949120

// stage-2 B' regions inside g_Bp (element offsets)
#define BW_BASE 0
#define BA_BASE 983040
#define BG_BASE 1572864
#define BV_BASE 2555904
#define BK_BASE 2654208

// ---------------- scratch ----------------
__device__ float g_Ccat[(size_t)T_LEN * NCAT];
__device__ float g_wfull[T_LEN * HN_DIM];
__device__ float g_afull[T_LEN * HN_DIM];
__device__ float g_gfull[T_LEN * HN_DIM];
__device__ float g_vmix[T_LEN * KVN_DIM];
__device__ float g_kmix[T_LEN * KVN_DIM];
__device__ float g_rr[T_LEN * HN_DIM];
__device__ float g_kf[T_LEN * KVN_DIM];
__device__ float g_vf[T_LEN * KVN_DIM];
__device__ float g_kk[T_LEN * KVN_DIM];
__device__ float g_wd[T_LEN * HN_DIM];
__device__ float g_bb[T_LEN * HN_DIM];
__device__ float g_coef[T_LEN * H_NUM];
__device__ float2 g_c12[T_LEN * H_NUM];
__device__ float g_y[T_LEN * HN_DIM];

__device__ __nv_bfloat16 g_Ap[(size_t)2048 * 3 * 2048];
__device__ __nv_bfloat16 g_Bp[(size_t)3 * 2048 * NCAT];

// ---------------- helpers ----------------
__device__ __forceinline__ float sigmoidf_(float x) { return 1.0f / (1.0f + expf(-x)); }

__device__ __forceinline__ float blockReduceSum128(float v, float* red) {
#pragma unroll
    for (int m = 16; m > 0; m >>= 1) v += __shfl_xor_sync(0xffffffffu, v, m);
    __syncthreads();
    if ((threadIdx.x & 31) == 0) red[threadIdx.x >> 5] = v;
    __syncthreads();
    return red[0] + red[1] + red[2] + red[3];
}

__device__ __forceinline__ void blockReduceSum3(float& a, float& b, float& c,
                                                float (*red)[3]) {
#pragma unroll
    for (int m = 16; m > 0; m >>= 1) {
        a += __shfl_xor_sync(0xffffffffu, a, m);
        b += __shfl_xor_sync(0xffffffffu, b, m);
        c += __shfl_xor_sync(0xffffffffu, c, m);
    }
    __syncthreads();
    if ((threadIdx.x & 31) == 0) {
        int w = threadIdx.x >> 5;
        red[w][0] = a;
        red[w][1] = b;
        red[w][2] = c;
    }
    __syncthreads();
    a = red[0][0] + red[1][0] + red[2][0] + red[3][0];
    b = red[0][1] + red[1][1] + red[2][1] + red[3][1];
    c = red[0][2] + red[1][2] + red[2][2] + red[3][2];
}

// packed f32x2 ops (sm_103a)
typedef unsigned long long ull;
__device__ __forceinline__ ull pack2(float x, float y) {
    ull r;
    asm("mov.b64 %0, {%1, %2};" : "=l"(r) : "f"(x), "f"(y));
    return r;
}
__device__ __forceinline__ float2 unpack2(ull v) {
    float x, y;
    asm("mov.b64 {%0, %1}, %2;" : "=f"(x), "=f"(y) : "l"(v));
    return make_float2(x, y);
}
__device__ __forceinline__ ull fma2_(ull a, ull b, ull c) {
    ull d;
    asm("fma.rn.f32x2 %0, %1, %2, %3;" : "=l"(d) : "l"(a), "l"(b), "l"(c));
    return d;
}
__device__ __forceinline__ ull mul2_(ull a, ull b) {
    ull d;
    asm("mul.rn.f32x2 %0, %1, %2;" : "=l"(d) : "l"(a), "l"(b));
    return d;
}

__device__ __forceinline__ uint32_t packsplit_hi(float a, float b) {
    __nv_bfloat162 h = __floats2bfloat162_rn(a, b);
    return *(uint32_t*)&h;
}
__device__ __forceinline__ uint32_t packsplit_lo(float a, float b, uint32_t hipack) {
    __nv_bfloat162* hp = (__nv_bfloat162*)&hipack;
    float ra = a - __bfloat162float(hp->x);
    float rb = b - __bfloat162float(hp->y);
    __nv_bfloat162 l = __floats2bfloat162_rn(ra, rb);
    return *(uint32_t*)&l;
}

// ---------------- split conversions ----------------
__global__ void splitAmask_kernel(const float* __restrict__ x, const float* __restrict__ mask,
                                  __nv_bfloat16* __restrict__ Ap, int n2) {
    int i = blockIdx.x * blockDim.x + threadIdx.x;
    if (i >= n2) return;
    int i2 = i * 2;
    int r = i2 >> 11, c = i2 & 2047;
    float2 xv = *(const float2*)&x[i2];
    float m = mask[r];
    float v0 = xv.x * m, v1 = xv.y * m;
    uint32_t hi = packsplit_hi(v0, v1);
    uint32_t lo = packsplit_lo(v0, v1, hi);
    size_t base = (size_t)r * 6144 + c;
    *(uint32_t*)&Ap[base] = hi;
    *(uint32_t*)&Ap[base + 2048] = lo;
    *(uint32_t*)&Ap[base + 4096] = hi;
}

__global__ void splitBcat_kernel(const float* __restrict__ W_r, const float* __restrict__ W_k,
                                 const float* __restrict__ W_v, const float* __restrict__ w1,
                                 const float* __restrict__ a1, const float* __restrict__ v1,
                                 const float* __restrict__ k1, const float* __restrict__ g1,
                                 __nv_bfloat16* __restrict__ Bp, int n2) {
    int i = blockIdx.x * blockDim.x + threadIdx.x;
    if (i >= n2) return;
    int i2 = i * 2;
    int r = i2 / NCAT, c = i2 - r * NCAT;
    const float* src;
    int off, ncols;
    if (c < 2048) { src = W_r; off = OFF_XR; ncols = 2048; }
    else if (c < 2560) { src = W_k; off = OFF_XK; ncols = 512; }
    else if (c < 3072) { src = W_v; off = OFF_XV; ncols = 512; }
    else if (c < 3232) { src = w1; off = OFF_TW; ncols = 160; }
    else if (c < 3328) { src = a1; off = OFF_TA; ncols = 96; }
    else if (c < 3392) { src = v1; off = OFF_TV; ncols = 64; }
    else if (c < 3456) { src = k1; off = OFF_TK; ncols = 64; }
    else { src = g1; off = OFF_TG; ncols = 160; }
    float2 xv = *(const float2*)&src[(size_t)r * ncols + (c - off)];
    uint32_t hi = packsplit_hi(xv.x, xv.y);
    uint32_t lo = packsplit_lo(xv.x, xv.y, hi);
    size_t base = (size_t)r * NCAT + c;
    *(uint32_t*)&Bp[base] = hi;
    *(uint32_t*)&Bp[base + (size_t)2048 * NCAT] = hi;
    *(uint32_t*)&Bp[base + (size_t)4096 * NCAT] = lo;
}

// generic B split (final projection)
__global__ void splitB_kernel(const float* __restrict__ B, __nv_bfloat16* __restrict__ Bp,
                              int K, int Ncols, int ldB, int colOff, int n2) {
    int i = blockIdx.x * blockDim.x + threadIdx.x;
    if (i >= n2) return;
    int i2 = i * 2;
    int r = i2 / Ncols, c = i2 - r * Ncols;
    float2 xv = *(const float2*)&B[i2];
    uint32_t hi = packsplit_hi(xv.x, xv.y);
    uint32_t lo = packsplit_lo(xv.x, xv.y, hi);
    size_t base = (size_t)r * ldB + colOff + c;
    *(uint32_t*)&Bp[base] = hi;
    *(uint32_t*)&Bp[base + (size_t)K * ldB] = hi;
    *(uint32_t*)&Bp[base + (size_t)2 * K * ldB] = lo;
}

// one fused kernel for ALL five stage-2 B matrices
__global__ void splitB2_kernel(const float* __restrict__ w2, const float* __restrict__ a2,
                               const float* __restrict__ g2, const float* __restrict__ v2,
                               const float* __restrict__ k2, __nv_bfloat16* __restrict__ Bp,
                               int n2) {
    int i = blockIdx.x * blockDim.x + threadIdx.x;
    if (i >= n2) return;
    int i2 = i * 2;
    const float* src;
    int K, N, local;
    size_t base;
    if (i2 < 327680) { src = w2; K = 160; N = 2048; base = BW_BASE; local = i2; }
    else if (i2 < 524288) { src = a2; K = 96; N = 2048; base = BA_BASE; local = i2 - 327680; }
    else if (i2 < 851968) { src = g2; K = 160; N = 2048; base = BG_BASE; local = i2 - 524288; }
    else if (i2 < 884736) { src = v2; K = 64; N = 512; base = BV_BASE; local = i2 - 851968; }
    else { src = k2; K = 64; N = 512; base = BK_BASE; local = i2 - 884736; }
    float2 xv = *(const float2*)&src[local];
    uint32_t hi = packsplit_hi(xv.x, xv.y);
    uint32_t lo = packsplit_lo(xv.x, xv.y, hi);
    size_t off = base + (size_t)local;
    *(uint32_t*)&Bp[off] = hi;
    *(uint32_t*)&Bp[off + (size_t)K * N] = hi;
    *(uint32_t*)&Bp[off + (size_t)2 * K * N] = lo;
}

// ---------------- fused act + stage-2 A-split from Ccat ----------------
__global__ void splitMids_kernel(const float* __restrict__ Ccat, __nv_bfloat16* __restrict__ Ap,
                                 int n2) {
    int i = blockIdx.x * blockDim.x + threadIdx.x;
    if (i >= n2) return;
    int i2 = i * 2;
    int t = i2 / NMID, c = i2 - t * NMID;
    const float* src = &Ccat[(size_t)t * NCAT + OFF_TW];
    float v0 = src[c], v1 = src[c + 1];
    int K, lc;
    size_t base;
    if (c < 160) {
        v0 = tanhf(v0); v1 = tanhf(v1);
        K = 160; base = APW_BASE; lc = c;
    } else if (c < 256) {
        K = 96; base = APA_BASE; lc = c - 160;
    } else if (c < 320) {
        K = 64; base = APV_BASE; lc = c - 256;
    } else if (c < 384) {
        K = 64; base = APK_BASE; lc = c - 320;
    } else {
        v0 = sigmoidf_(v0); v1 = sigmoidf_(v1);
        K = 160; base = APG_BASE; lc = c - 384;
    }
    uint32_t hi = packsplit_hi(v0, v1);
    uint32_t lo = packsplit_lo(v0, v1, hi);
    size_t off = base + (size_t)t * (3 * K) + lc;
    *(uint32_t*)&Ap[off] = hi;
    *(uint32_t*)&Ap[off + K] = lo;
    *(uint32_t*)&Ap[off + 2 * K] = hi;
}

// ---------------- fused merge + final A-split ----------------
__global__ void mergeSplitA_kernel(const float* __restrict__ y, const float* __restrict__ coef,
                                   const float* __restrict__ vf, const float* __restrict__ gbuf,
                                   __nv_bfloat16* __restrict__ Ap, int n2) {
    int i = blockIdx.x * blockDim.x + threadIdx.x;
    if (i >= n2) return;
    int i2 = i * 2;
    int t = i2 >> 11, hn = i2 & 2047;
    int h = hn >> 7, nn = hn & 127;
    float cf = coef[t * H_NUM + h];
    const float* vp = &vf[t * KVN_DIM + (h >> 2) * 128 + nn];
    float2 yv = *(const float2*)&y[i2];
    float2 gv = *(const float2*)&gbuf[i2];
    float v0 = (yv.x + cf * vp[0]) * gv.x;
    float v1 = (yv.y + cf * vp[1]) * gv.y;
    uint32_t hi = packsplit_hi(v0, v1);
    uint32_t lo = packsplit_lo(v0, v1, hi);
    size_t base = (size_t)t * 6144 + hn;
    *(uint32_t*)&Ap[base] = hi;
    *(uint32_t*)&Ap[base + 2048] = lo;
    *(uint32_t*)&Ap[base + 4096] = hi;
}

// ---------------- bf16 tensor-core GEMM, 3-stage cp.async pipeline ----------------
#define LDA_S 40
#define LDB_S 136
#define NSTAGE 3

__global__ __launch_bounds__(256) void bf16_gemm_kernel(
    const __nv_bfloat16* __restrict__ A, const __nv_bfloat16* __restrict__ B,
    float* __restrict__ C, int M, int N, int K3, int ldB, int ldC) {
    __shared__ __align__(16) __nv_bfloat16 As[NSTAGE][128 * LDA_S];
    __shared__ __align__(16) __nv_bfloat16 Bs[NSTAGE][32 * LDB_S];

    const int tid = threadIdx.x;
    const int bm = blockIdx.y * 128;
    const int bn = blockIdx.x * 128;
    const int warp = tid >> 5;
    const int lane = tid & 31;
    const int wm = warp & 3;
    const int wn = warp >> 2;

    const int ar = tid >> 2;
    const int ac = (tid & 3) * 8;
    const int br = tid >> 4;
    const int bc = (tid & 15) * 8;
    const int bsz = ((bn + bc) < N) ? 16 : 0;

    float c[2][8][4];
#pragma unroll
    for (int mi = 0; mi < 2; mi++)
#pragma unroll
        for (int ni = 0; ni < 8; ni++)
#pragma unroll
            for (int q = 0; q < 4; q++) c[mi][ni][q] = 0.0f;

    const int KT = K3 >> 5;

    auto load_stage = [&](int st, int kt) {
        int k0 = kt * 32;
#pragma unroll
        for (int it = 0; it < 2; it++) {
            const __nv_bfloat16* src = A + (size_t)(bm + ar + it * 64) * K3 + k0 + ac;
            uint32_t dst = (uint32_t)__cvta_generic_to_shared(&As[st][(ar + it * 64) * LDA_S + ac]);
            asm volatile("cp.async.ca.shared.global [%0], [%1], 16;\n" ::"r"(dst), "l"(src));
        }
#pragma unroll
        for (int it = 0; it < 2; it++) {
            const __nv_bfloat16* src = B + (size_t)(k0 + br + it * 16) * ldB + bn + bc;
            uint32_t dst = (uint32_t)__cvta_generic_to_shared(&Bs[st][(br + it * 16) * LDB_S + bc]);
            asm volatile("cp.async.ca.shared.global [%0], [%1], 16, %2;\n" ::"r"(dst), "l"(src),
                         "r"(bsz));
        }
        asm volatile("cp.async.commit_group;\n");
    };

    auto compute_stage = [&](int st) {
#pragma unroll
        for (int kk = 0; kk < 32; kk += 16) {
            uint32_t af[2][4];
#pragma unroll
            for (int mi = 0; mi < 2; mi++) {
                uint32_t addr = (uint32_t)__cvta_generic_to_shared(
                    &As[st][(wm * 32 + mi * 16 + (lane & 15)) * LDA_S + kk + (lane >> 4) * 8]);
                asm volatile("ldmatrix.sync.aligned.m8n8.x4.shared.b16 {%0,%1,%2,%3}, [%4];\n"
                             : "=r"(af[mi][0]), "=r"(af[mi][1]), "=r"(af[mi][2]), "=r"(af[mi][3])
                             : "r"(addr));
            }
            uint32_t bfr[8][2];
#pragma unroll
            for (int p = 0; p < 4; p++) {
                uint32_t addr = (uint32_t)__cvta_generic_to_shared(
                    &Bs[st][(kk + (lane & 15)) * LDB_S + wn * 64 + p * 16 + (lane >> 4) * 8]);
                uint32_t b0, b1, b2, b3;
                asm volatile("ldmatrix.sync.aligned.m8n8.x4.trans.shared.b16 {%0,%1,%2,%3}, [%4];\n"
                             : "=r"(b0), "=r"(b1), "=r"(b2), "=r"(b3)
                             : "r"(addr));
                bfr[p * 2][0] = b0;
                bfr[p * 2][1] = b1;
                bfr[p * 2 + 1][0] = b2;
                bfr[p * 2 + 1][1] = b3;
            }
#pragma unroll
            for (int mi = 0; mi < 2; mi++)
#pragma unroll
                for (int ni = 0; ni < 8; ni++) {
                    asm volatile(
                        "mma.sync.aligned.m16n8k16.row.col.f32.bf16.bf16.f32 "
                        "{%0,%1,%2,%3}, {%4,%5,%6,%7}, {%8,%9}, {%0,%1,%2,%3};\n"
                        : "+f"(c[mi][ni][0]), "+f"(c[mi][ni][1]), "+f"(c[mi][ni][2]),
                          "+f"(c[mi][ni][3])
                        : "r"(af[mi][0]), "r"(af[mi][1]), "r"(af[mi][2]), "r"(af[mi][3]),
                          "r"(bfr[ni][0]), "r"(bfr[ni][1]));
                }
        }
    };

    load_stage(0, 0);
    if (KT > 1) load_stage(1, 1);
    for (int kt = 0; kt < KT; kt++) {
        if (kt + 2 < KT) {
            load_stage((kt + 2) % NSTAGE, kt + 2);
            asm volatile("cp.async.wait_group 2;\n");
        } else if (kt + 1 < KT) {
            asm volatile("cp.async.wait_group 1;\n");
        } else {
            asm volatile("cp.async.wait_group 0;\n");
        }
        __syncthreads();
        compute_stage(kt % NSTAGE);
        __syncthreads();
    }

#pragma unroll
    for (int mi = 0; mi < 2; mi++) {
        int row = bm + wm * 32 + mi * 16 + (lane >> 2);
#pragma unroll
        for (int ni = 0; ni < 8; ni++) {
            int col = bn + wn * 64 + ni * 8 + (lane & 3) * 2;
            if (col < N) {
                C[(size_t)row * ldC + col] = c[mi][ni][0];
                C[(size_t)row * ldC + col + 1] = c[mi][ni][1];
                C[(size_t)(row + 8) * ldC + col] = c[mi][ni][2];
                C[(size_t)(row + 8) * ldC + col + 1] = c[mi][ni][3];
            }
        }
    }
}

// ---------------- postprocess per (t, kvh) ----------------
__global__ void pp_kv_kernel(const float* __restrict__ Ccat,
                             const float* __restrict__ kmix, const float* __restrict__ vmix,
                             const float* __restrict__ k_first, const float* __restrict__ v_first,
                             const float* __restrict__ k0, const float* __restrict__ v0,
                             const float* __restrict__ knw, const float* __restrict__ cosb,
                             const float* __restrict__ sinb,
                             float* __restrict__ kf, float* __restrict__ vfout,
                             float* __restrict__ kkout) {
    int t = blockIdx.x, kvh = blockIdx.y, n = threadIdx.x;
    int idx = t * KVN_DIM + kvh * 128 + n;
    size_t cidx = (size_t)t * NCAT + kvh * 128 + n;
    __shared__ float shk[128];
    __shared__ float red[4];

    float k = Ccat[cidx + OFF_XK];
    float ss = blockReduceSum128(k * k, red);
    float kn = knw[n] * k * rsqrtf(ss * (1.0f / 128.0f) + 1e-6f);
    shk[n] = kn;
    __syncthreads();
    float rh = (n < 64) ? -shk[n + 64] : shk[n - 64];
    float c = cosb[t * 128 + n], s = sinb[t * 128 + n];
    float kr = fmaf(kn, c, rh * s);

    float kfv = kr + (k_first[idx] - kr) * sigmoidf_(k0[kvh * 128 + n] + kmix[idx]);
    float vv = Ccat[cidx + OFF_XV];
    float vfv = vv + (v_first[idx] - vv) * sigmoidf_(v0[kvh * 128 + n] + vmix[idx]);

    float nrm2 = blockReduceSum128(kfv * kfv, red);
    float denom = fmaxf(sqrtf(nrm2), 1e-12f);

    kf[idx] = kfv;
    vfout[idx] = vfv;
    kkout[idx] = kfv / denom;
}

// ---------------- postprocess per (t, h) ----------------
__global__ void pp_h_kernel(const float* __restrict__ Ccat, const float* __restrict__ wfull,
                            const float* __restrict__ afull,
                            const float* __restrict__ w0, const float* __restrict__ a0,
                            const float* __restrict__ kkbuf, const float* __restrict__ kfbuf,
                            const float* __restrict__ rnw, const float* __restrict__ cosb,
                            const float* __restrict__ sinb, const float* __restrict__ r_k,
                            float* __restrict__ rout, float* __restrict__ wdout,
                            float* __restrict__ bbout, float* __restrict__ coef,
                            float2* __restrict__ c12) {
    int t = blockIdx.x, h = blockIdx.y, n = threadIdx.x;
    int hn = h * 128 + n;
    int idx = t * HN_DIM + hn;
    __shared__ float shr[128];
    __shared__ float red[4];
    __shared__ float red3[4][3];

    float r = Ccat[(size_t)t * NCAT + OFF_XR + hn];
    float ss = blockReduceSum128(r * r, red);
    float rn = rnw[n] * r * rsqrtf(ss * (1.0f / 128.0f) + 1e-6f);
    shr[n] = rn;
    __syncthreads();
    float rh = (n < 64) ? -shr[n + 64] : shr[n - 64];
    float c = cosb[t * 128 + n], s = sinb[t * 128 + n];
    float rr = fmaf(rn, c, rh * s);
    rout[idx] = rr;

    float z = w0[hn] + wfull[idx];
    float u = -z;
    float sp = fmaxf(u, 0.0f) + log1pf(expf(-fabsf(u)));
    float w = -sp - 0.5f;
    wdout[idx] = expf(-expf(w));

    float a = sigmoidf_(a0[hn] + afull[idx]);
    int kvidx = t * KVN_DIM + (h >> 2) * 128 + n;
    float kfv = kfbuf[kvidx];
    float bbv = kkbuf[kvidx] * a;
    bbout[idx] = bbv;

    float p0 = rr * kfv * r_k[hn];
    float p1 = bbv * rr;
    float p2 = kfv * rr;
    blockReduceSum3(p0, p1, p2, red3);
    if (n == 0) {
        coef[t * H_NUM + h] = p0;
        c12[t * H_NUM + h] = make_float2(p1, p2);
    }
}

// ---------------- sequential scan (v4: warp-autonomous + depth-4 prefetch) ----------------
// grid (16 h, 32 rowgroups), 32 threads = 1 warp. Warp owns 4 rows of S; lane owns a
// 4-wide j-slice. Depth-4 circular register prefetch hides DRAM latency (~4 steps).
__global__ __launch_bounds__(32) void scan_kernel(const float* __restrict__ wdec,
                                                  const float* __restrict__ bb,
                                                  const float* __restrict__ kk,
                                                  const float* __restrict__ kf,
                                                  const float* __restrict__ rr,
                                                  const float* __restrict__ vf,
                                                  const float2* __restrict__ c12,
                                                  float* __restrict__ y) {
    const int h = blockIdx.x;
    const int rg = blockIdx.y;
    const int lane = threadIdx.x;
    const int kvh = h >> 2;

    const int hoff = h * 128 + lane * 4;
    const int koff = kvh * 128 + lane * 4;
    const int voff = kvh * 128 + rg * 4;
    float* py = y + h * 128 + rg * 4;

    ull S2[4][2];
#pragma unroll
    for (int i = 0; i < 4; i++) { S2[i][0] = 0ull; S2[i][1] = 0ull; }

    float4 Pw[4], Pb[4], Pr[4], Pk[4], Pf[4], Pv[4];
    float2 Pc[4];
#pragma unroll
    for (int d = 0; d < 4; d++) {
        size_t oH = (size_t)d * HN_DIM;
        size_t oKV = (size_t)d * KVN_DIM;
        Pw[d] = *(const float4*)&wdec[oH + hoff];
        Pb[d] = *(const float4*)&bb[oH + hoff];
        Pr[d] = *(const float4*)&rr[oH + hoff];
        Pk[d] = *(const float4*)&kk[oKV + koff];
        Pf[d] = *(const float4*)&kf[oKV + koff];
        Pv[d] = *(const float4*)&vf[oKV + voff];
        Pc[d] = c12[d * H_NUM + h];
    }

    for (int t = 0; t < T_LEN; t += 4) {
#pragma unroll
        for (int u = 0; u < 4; u++) {
            // consume slot u (data for step t+u)
            float4 w4 = Pw[u], b4 = Pb[u], r4 = Pr[u], k4 = Pk[u], f4 = Pf[u], v4 = Pv[u];
            float2 cc = Pc[u];

            // refill slot u with step t+u+4 (4 steps of latency tolerance)
            int tn = t + u + 4;
            if (tn > T_LEN - 1) tn = T_LEN - 1;
            size_t oH = (size_t)tn * HN_DIM;
            size_t oKV = (size_t)tn * KVN_DIM;
            Pw[u] = *(const float4*)&wdec[oH + hoff];
            Pb[u] = *(const float4*)&bb[oH + hoff];
            Pr[u] = *(const float4*)&rr[oH + hoff];
            Pk[u] = *(const float4*)&kk[oKV + koff];
            Pf[u] = *(const float4*)&kf[oKV + koff];
            Pv[u] = *(const float4*)&vf[oKV + voff];
            Pc[u] = c12[tn * H_NUM + h];

            // pack halves
            ull wA = pack2(w4.x, w4.y), wB = pack2(w4.z, w4.w);
            ull bA = pack2(b4.x, b4.y), bB = pack2(b4.z, b4.w);
            ull kA = pack2(k4.x, k4.y), kB = pack2(k4.z, k4.w);
            ull fA = pack2(f4.x, f4.y), fB = pack2(f4.z, f4.w);
            ull wrA = pack2(w4.x * r4.x, w4.y * r4.y);
            ull wrB = pack2(w4.z * r4.z, w4.w * r4.w);

            // per-row partial dots: sa_i = S_i . kk ; d1_i = S_i . (w*r)
            float sa[4], d1[4];
#pragma unroll
            for (int i = 0; i < 4; i++) {
                ull sdp = fma2_(S2[i][1], kB, mul2_(S2[i][0], kA));
                float2 su = unpack2(sdp);
                sa[i] = su.x + su.y;
                ull ddp = fma2_(S2[i][1], wrB, mul2_(S2[i][0], wrA));
                float2 du = unpack2(ddp);
                d1[i] = du.x + du.y;
            }

#pragma unroll
            for (int m = 16; m > 0; m >>= 1) {
                sa[0] += __shfl_xor_sync(0xffffffffu, sa[0], m);
                sa[1] += __shfl_xor_sync(0xffffffffu, sa[1], m);
                sa[2] += __shfl_xor_sync(0xffffffffu, sa[2], m);
                sa[3] += __shfl_xor_sync(0xffffffffu, sa[3], m);
                d1[0] += __shfl_xor_sync(0xffffffffu, d1[0], m);
                d1[1] += __shfl_xor_sync(0xffffffffu, d1[1], m);
                d1[2] += __shfl_xor_sync(0xffffffffu, d1[2], m);
                d1[3] += __shfl_xor_sync(0xffffffffu, d1[3], m);
            }
#pragma unroll
            for (int i = 0; i < 4; i++) sa[i] = -sa[i];

            if (lane == 0) {
                float4 yo;
                yo.x = fmaf(sa[0], cc.x, fmaf(v4.x, cc.y, d1[0]));
                yo.y = fmaf(sa[1], cc.x, fmaf(v4.y, cc.y, d1[1]));
                yo.z = fmaf(sa[2], cc.x, fmaf(v4.z, cc.y, d1[2]));
                yo.w = fmaf(sa[3], cc.x, fmaf(v4.w, cc.y, d1[3]));
                *(float4*)&py[(size_t)(t + u) * HN_DIM] = yo;
            }

            const float vv[4] = {v4.x, v4.y, v4.z, v4.w};
#pragma unroll
            for (int i = 0; i < 4; i++) {
                ull sai = pack2(sa[i], sa[i]);
                ull vvi = pack2(vv[i], vv[i]);
                S2[i][0] = fma2_(S2[i][0], wA, fma2_(sai, bA, mul2_(vvi, fA)));
                S2[i][1] = fma2_(S2[i][1], wB, fma2_(sai, bB, mul2_(vvi, fB)));
            }
        }
    }
}

// ---------------- launch ----------------
static float* symAddrF(const void* sym) {
    void* p = nullptr;
    cudaGetSymbolAddress(&p, sym);
    return (float*)p;
}
static float2* symAddrF2(const void* sym) {
    void* p = nullptr;
    cudaGetSymbolAddress(&p, sym);
    return (float2*)p;
}
static __nv_bfloat16* symAddrB(const void* sym) {
    void* p = nullptr;
    cudaGetSymbolAddress(&p, sym);
    return (__nv_bfloat16*)p;
}

extern "C" void kernel_launch(void* const* d_in, const int* in_sizes, int n_in,
                              void* d_out, int out_size) {
    const float* x = (const float*)d_in[0];
    const float* v_first = (const float*)d_in[1];
    const float* k_first = (const float*)d_in[2];
    const float* amask = (const float*)d_in[3];
    const float* cosb = (const float*)d_in[4];
    const float* sinb = (const float*)d_in[5];
    const float* w0 = (const float*)d_in[6];
    const float* w1 = (const float*)d_in[7];
    const float* w2 = (const float*)d_in[8];
    const float* a0 = (const float*)d_in[9];
    const float* a1 = (const float*)d_in[10];
    const float* a2 = (const float*)d_in[11];
    const float* v0 = (const float*)d_in[12];
    const float* v1 = (const float*)d_in[13];
    const float* v2 = (const float*)d_in[14];
    const float* k0 = (const float*)d_in[15];
    const float* k1 = (const float*)d_in[16];
    const float* k2 = (const float*)d_in[17];
    const float* g1 = (const float*)d_in[18];
    const float* g2 = (const float*)d_in[19];
    const float* r_k = (const float*)d_in[20];
    const float* r_norm_w = (const float*)d_in[21];
    const float* k_norm_w = (const float*)d_in[22];
    const float* W_r = (const float*)d_in[23];
    const float* W_k = (const float*)d_in[24];
    const float* W_v = (const float*)d_in[25];
    const float* W_o = (const float*)d_in[26];
    float* out = (float*)d_out;

    float* Ccat = symAddrF(g_Ccat);
    float* wfull = symAddrF(g_wfull);
    float* afull = symAddrF(g_afull);
    float* gfull = symAddrF(g_gfull);
    float* vmix = symAddrF(g_vmix);
    float* kmix = symAddrF(g_kmix);
    float* rrb = symAddrF(g_rr);
    float* kf = symAddrF(g_kf);
    float* vf = symAddrF(g_vf);
    float* kkb = symAddrF(g_kk);
    float* wd = symAddrF(g_wd);
    float* bbb = symAddrF(g_bb);
    float* coef = symAddrF(g_coef);
    float2* c12 = symAddrF2(g_c12);
    float* yb = symAddrF(g_y);
    __nv_bfloat16* Ap = symAddrB(g_Ap);
    __nv_bfloat16* Bp = symAddrB(g_Bp);

    // ---- stage 1 ----
    const int NTC2 = T_LEN * C_DIM / 2;
    splitAmask_kernel<<<(NTC2 + 255) / 256, 256>>>(x, amask, Ap, NTC2);

    const int NB2 = T_LEN * NCAT / 2;
    splitBcat_kernel<<<(NB2 + 255) / 256, 256>>>(W_r, W_k, W_v, w1, a1, v1, k1, g1, Bp, NB2);

    {
        dim3 grid((NCAT + 127) / 128, 2048 / 128);
        bf16_gemm_kernel<<<grid, 256>>>(Ap, Bp, Ccat, 2048, NCAT, 6144, NCAT, NCAT);
    }

    // ---- fused activations + stage-2 A splits ----
    const int NMIDS2 = T_LEN * NMID / 2;
    splitMids_kernel<<<(NMIDS2 + 255) / 256, 256>>>(Ccat, Ap, NMIDS2);

    // ---- stage 2: one fused B split + 5 GEMMs ----
    {
        const int n2 = 917504 / 2;
        splitB2_kernel<<<(n2 + 255) / 256, 256>>>(w2, a2, g2, v2, k2, Bp, n2);
    }
    auto gemm2 = [&](size_t aBase, size_t bBase, int K, float* C, int N) {
        dim3 grid((N + 127) / 128, 2048 / 128);
        bf16_gemm_kernel<<<grid, 256>>>(Ap + aBase, Bp + bBase, C, 2048, N, 3 * K, N, N);
    };
    gemm2(APW_BASE, BW_BASE, 160, wfull, 2048);
    gemm2(APA_BASE, BA_BASE, 96, afull, 2048);
    gemm2(APG_BASE, BG_BASE, 160, gfull, 2048);
    gemm2(APV_BASE, BV_BASE, 64, vmix, 512);
    gemm2(APK_BASE, BK_BASE, 64, kmix, 512);

    // ---- postprocess ----
    pp_kv_kernel<<<dim3(T_LEN, KVH_NUM), 128>>>(Ccat, kmix, vmix, k_first, v_first,
                                                k0, v0, k_norm_w, cosb, sinb,
                                                kf, vf, kkb);
    pp_h_kernel<<<dim3(T_LEN, H_NUM), 128>>>(Ccat, wfull, afull, w0, a0, kkb, kf,
                                             r_norm_w, cosb, sinb, r_k,
                                             rrb, wd, bbb, coef, c12);

    // ---- sequential scan: 512 independent warps, depth-4 prefetch ----
    scan_kernel<<<dim3(H_NUM, 32), 32>>>(wd, bbb, kkb, kf, rrb, vf, c12, yb);

    // ---- fused merge + final A split ----
    const int NHN2 = T_LEN * HN_DIM / 2;
    mergeSplitA_kernel<<<(NHN2 + 255) / 256, 256>>>(yb, coef, vf, gfull, Ap, NHN2);

    // ---- final projection ----
    {
        int n2 = 2048 * 2048 / 2;
        splitB_kernel<<<(n2 + 255) / 256, 256>>>(W_o, Bp, 2048, 2048, 2048, 0, n2);
        dim3 grid(2048 / 128, 2048 / 128);
        bf16_gemm_kernel<<<grid, 256>>>(Ap, Bp, out, 2048, 2048, 6144, 2048, 2048);
    }
}